// round 5
// baseline (speedup 1.0000x reference)
#include <cuda_runtime.h>
#include <math_constants.h>

#define N_TOK 32768   // B*T = 8*4096
#define DIM   128
#define KCB   1024
#define NCB   8

#define MT    32      // tokens per block
#define KTILE 64      // codewords per chunk
#define TPB   128     // threads per block (8 token-groups x 16 cw-lanes)
#define RPAD  132     // padded row stride in floats (conflict-free LDS.128)

__device__ float  g_residual[N_TOK * DIM];
__device__ float  g_cnorm[NCB * KCB];
__device__ int    g_codes[N_TOK * NCB];
__device__ double g_loss[NCB];

__global__ void zero_loss_kernel() {
    if (threadIdx.x < NCB) g_loss[threadIdx.x] = 0.0;
}

__global__ void cnorm_kernel(const float* __restrict__ cbs) {
    int idx = blockIdx.x * blockDim.x + threadIdx.x;
    if (idx >= NCB * KCB) return;
    const float4* v = (const float4*)(cbs + (size_t)idx * DIM);
    float4 a = make_float4(0.f, 0.f, 0.f, 0.f);
#pragma unroll
    for (int i = 0; i < DIM / 4; i++) {
        float4 x = v[i];
        a.x = fmaf(x.x, x.x, a.x);
        a.y = fmaf(x.y, x.y, a.y);
        a.z = fmaf(x.z, x.z, a.z);
        a.w = fmaf(x.w, x.w, a.w);
    }
    g_cnorm[idx] = (a.x + a.y) + (a.z + a.w);
}

// Register-blocked distance pass + fused argmin + residual update.
// Thread (tg, cg): tg = tid/16 (token group, 4 tokens), cg = tid%16 (cw lane).
// Thread's codewords within a chunk: cg + 16*jc, jc = 0..3 (strided; keeps
// 16 lanes on 16 consecutive smem rows -> 2 wavefronts per LDS.128, the
// bandwidth floor).
__global__ void __launch_bounds__(TPB)
rvq_step_kernel(const float* __restrict__ emb,
                const float* __restrict__ cb,   // this codebook [K, D]
                int cb_idx, int use_emb) {
    __shared__ float s_r[MT * RPAD];
    __shared__ float s_c[KTILE * RPAD];
    __shared__ float s_cn[KTILE];

    const float* src = use_emb ? emb : (const float*)g_residual;
    const float* cn  = g_cnorm + (size_t)cb_idx * KCB;

    const int tid = threadIdx.x;
    const int tg  = tid >> 4;       // 0..7
    const int cg  = tid & 15;       // 0..15
    const int tok0 = blockIdx.x * MT;

    // ---- load residual tile [MT x DIM] into padded smem ----
    {
        const int nvec = MT * (DIM / 4);           // 1024 float4
#pragma unroll
        for (int t = 0; t < nvec / TPB; t++) {
            int idx = tid + t * TPB;
            int row = idx >> 5;                    // /32
            int col = idx & 31;
            float4 v = *(const float4*)(src + ((size_t)(tok0 + row)) * DIM + col * 4);
            *(float4*)(s_r + row * RPAD + col * 4) = v;
        }
    }
    __syncthreads();

    // ---- rn for this thread's 4 tokens (same float4-tree order as before) ----
    float rn[4];
#pragma unroll
    for (int jm = 0; jm < 4; jm++) {
        const float* rr = s_r + (tg * 4 + jm) * RPAD;
        float4 a = make_float4(0.f, 0.f, 0.f, 0.f);
#pragma unroll
        for (int i = 0; i < DIM / 4; i++) {
            float4 x = *(const float4*)(rr + i * 4);
            a.x = fmaf(x.x, x.x, a.x);
            a.y = fmaf(x.y, x.y, a.y);
            a.z = fmaf(x.z, x.z, a.z);
            a.w = fmaf(x.w, x.w, a.w);
        }
        rn[jm] = (a.x + a.y) + (a.z + a.w);
    }

    float bestd[4] = {CUDART_INF_F, CUDART_INF_F, CUDART_INF_F, CUDART_INF_F};
    int   bestk[4] = {0, 0, 0, 0};

#pragma unroll 1
    for (int chunk = 0; chunk < KCB; chunk += KTILE) {
        __syncthreads();
        // cooperative load of codeword chunk [KTILE x DIM] (padded rows)
        {
            const int nvec = KTILE * (DIM / 4);    // 2048 float4
#pragma unroll
            for (int t = 0; t < nvec / TPB; t++) {
                int idx = tid + t * TPB;
                int row = idx >> 5;
                int col = idx & 31;
                float4 v = *(const float4*)(cb + ((size_t)(chunk + row)) * DIM + col * 4);
                *(float4*)(s_c + row * RPAD + col * 4) = v;
            }
            if (tid < KTILE) s_cn[tid] = cn[chunk + tid];
        }
        __syncthreads();

        float4 acc[4][4];   // [jm][jc]
#pragma unroll
        for (int jm = 0; jm < 4; jm++)
#pragma unroll
            for (int jc = 0; jc < 4; jc++)
                acc[jm][jc] = make_float4(0.f, 0.f, 0.f, 0.f);

        const float* rbase = s_r + (tg * 4) * RPAD;
        const float* cbase = s_c + cg * RPAD;

#pragma unroll 2
        for (int i = 0; i < DIM / 4; i++) {
            float4 rf[4], cf[4];
#pragma unroll
            for (int jm = 0; jm < 4; jm++)
                rf[jm] = *(const float4*)(rbase + jm * RPAD + i * 4);
#pragma unroll
            for (int jc = 0; jc < 4; jc++)
                cf[jc] = *(const float4*)(cbase + jc * 16 * RPAD + i * 4);
#pragma unroll
            for (int jm = 0; jm < 4; jm++) {
#pragma unroll
                for (int jc = 0; jc < 4; jc++) {
                    acc[jm][jc].x = fmaf(rf[jm].x, cf[jc].x, acc[jm][jc].x);
                    acc[jm][jc].y = fmaf(rf[jm].y, cf[jc].y, acc[jm][jc].y);
                    acc[jm][jc].z = fmaf(rf[jm].z, cf[jc].z, acc[jm][jc].z);
                    acc[jm][jc].w = fmaf(rf[jm].w, cf[jc].w, acc[jm][jc].w);
                }
            }
        }

        // distances + running first-min (k ascending within thread subset)
#pragma unroll
        for (int jm = 0; jm < 4; jm++) {
#pragma unroll
            for (int jc = 0; jc < 4; jc++) {
                float4 a = acc[jm][jc];
                float dot = (a.x + a.y) + (a.z + a.w);
                float d = fmaf(-2.f, dot, rn[jm]) + s_cn[cg + jc * 16];
                int k = chunk + cg + jc * 16;
                if (d < bestd[jm]) { bestd[jm] = d; bestk[jm] = k; }
            }
        }
    }

    // ---- cross-lane reduction over the 16 cw-lanes of this token group ----
    // (min d; tie -> min k). Lanes of a tg are 16 consecutive threads.
#pragma unroll
    for (int jm = 0; jm < 4; jm++) {
        float bd = bestd[jm];
        int   bk = bestk[jm];
#pragma unroll
        for (int off = 8; off; off >>= 1) {
            float od = __shfl_xor_sync(0xFFFFFFFFu, bd, off, 16);
            int   ok = __shfl_xor_sync(0xFFFFFFFFu, bk, off, 16);
            if (od < bd || (od == bd && ok < bk)) { bd = od; bk = ok; }
        }
        bestd[jm] = bd;
        bestk[jm] = bk;
    }

    // ---- epilogue: lane cg==0 updates residual / codes / loss for 4 tokens ----
    if (cg == 0) {
        double lsum = 0.0;
#pragma unroll 1
        for (int jm = 0; jm < 4; jm++) {
            int n = tok0 + tg * 4 + jm;
            int k = bestk[jm];
            const float4* qv = (const float4*)(cb + (size_t)k * DIM);
            const float*  rr = s_r + (tg * 4 + jm) * RPAD;
            float4* rv = (float4*)(g_residual + (size_t)n * DIM);
#pragma unroll
            for (int i = 0; i < DIM / 4; i++) {
                float4 r = *(const float4*)(rr + i * 4);
                float4 q = qv[i];
                r.x -= q.x; r.y -= q.y; r.z -= q.z; r.w -= q.w;
                lsum += (double)r.x * (double)r.x;
                lsum += (double)r.y * (double)r.y;
                lsum += (double)r.z * (double)r.z;
                lsum += (double)r.w * (double)r.w;
                rv[i] = r;
            }
            g_codes[n * NCB + cb_idx] = k;
        }
        atomicAdd(&g_loss[cb_idx], lsum);
    }
}

__global__ void finalize_kernel(const float* __restrict__ emb,
                                const float* __restrict__ cbs,
                                float* oc, float* oq, float* ol) {
    int n = blockIdx.x * blockDim.x + threadIdx.x;
    if (n >= N_TOK) return;

    float4 q[DIM / 4];
#pragma unroll
    for (int i = 0; i < DIM / 4; i++) q[i] = make_float4(0.f, 0.f, 0.f, 0.f);

#pragma unroll 1
    for (int c = 0; c < NCB; c++) {
        int k = g_codes[n * NCB + c];
        const float4* w = (const float4*)(cbs + ((size_t)c * KCB + k) * DIM);
#pragma unroll
        for (int i = 0; i < DIM / 4; i++) {
            float4 x = w[i];
            q[i].x += x.x; q[i].y += x.y; q[i].z += x.z; q[i].w += x.w;
        }
        if (oc) oc[n * NCB + c] = (float)k;
    }

    if (oq) {
        const float4* ev = (const float4*)(emb + (size_t)n * DIM);
        float4* ov = (float4*)(oq + (size_t)n * DIM);
#pragma unroll
        for (int i = 0; i < DIM / 4; i++) {
            float4 e = ev[i];
            float4 o;
            o.x = e.x + (q[i].x - e.x);
            o.y = e.y + (q[i].y - e.y);
            o.z = e.z + (q[i].z - e.z);
            o.w = e.w + (q[i].w - e.w);
            ov[i] = o;
        }
    }

    if (n == 0 && ol) {
        float l = 0.f;
#pragma unroll 1
        for (int c = 0; c < NCB; c++)
            l = l + (float)(g_loss[c] / (double)((size_t)N_TOK * DIM));
        *ol = l / (float)NCB;
    }
}

extern "C" void kernel_launch(void* const* d_in, const int* in_sizes, int n_in,
                              void* d_out, int out_size) {
    const float* emb = (const float*)d_in[0];  // embeddings [8,4096,128] f32
    const float* cbs = (const float*)d_in[1];  // codebooks  [8,1024,128] f32
    float* out = (float*)d_out;

    const long CODES_ELEMS = (long)N_TOK * NCB;        // 262144
    const long QUANT_ELEMS = (long)N_TOK * DIM;        // 4194304
    const long TOTAL = CODES_ELEMS + QUANT_ELEMS + 1;  // 4456449

    float *oc = nullptr, *oq = nullptr, *ol = nullptr;
    if ((long)out_size == TOTAL) {
        oc = out; oq = out + CODES_ELEMS; ol = out + CODES_ELEMS + QUANT_ELEMS;
    } else if ((long)out_size == QUANT_ELEMS) {
        oq = out;
    } else if ((long)out_size == CODES_ELEMS) {
        oc = out;
    } else if (out_size == 1) {
        ol = out;
    } else {
        oc = out;
        if ((long)out_size >= CODES_ELEMS + QUANT_ELEMS) oq = out + CODES_ELEMS;
        if ((long)out_size >= TOTAL) ol = out + CODES_ELEMS + QUANT_ELEMS;
    }

    zero_loss_kernel<<<1, 32>>>();
    cnorm_kernel<<<(NCB * KCB + 127) / 128, 128>>>(cbs);

    for (int c = 0; c < NCB; c++) {
        const float* cb = cbs + (size_t)c * KCB * DIM;
        rvq_step_kernel<<<N_TOK / MT, TPB>>>(emb, cb, c, c == 0 ? 1 : 0);
    }

    finalize_kernel<<<(N_TOK + 127) / 128, 128>>>(emb, cbs, oc, oq, ol);
}

// round 10
// speedup vs baseline: 1.3874x; 1.3874x over previous
#include <cuda_runtime.h>
#include <math_constants.h>

#define N_TOK 32768   // B*T = 8*4096
#define DIM   128
#define KCB   1024
#define NCB   8

#define MT    16      // tokens per block (4 warps x 4 tokens)
#define KTILE 64      // codewords per smem chunk
#define TPB   128     // 4 warps; warp w owns tokens [w*4, w*4+4), all 32 cw-lanes
#define RPAD  132     // padded row stride (floats): conflict-free strided LDS.128

__device__ float  g_residual[N_TOK * DIM];
__device__ float  g_cnorm[NCB * KCB];
__device__ int    g_codes[N_TOK * NCB];
__device__ double g_loss[NCB];

__global__ void zero_loss_kernel() {
    if (threadIdx.x < NCB) g_loss[threadIdx.x] = 0.0;
}

__global__ void cnorm_kernel(const float* __restrict__ cbs) {
    int idx = blockIdx.x * blockDim.x + threadIdx.x;
    if (idx >= NCB * KCB) return;
    const float4* v = (const float4*)(cbs + (size_t)idx * DIM);
    float4 a = make_float4(0.f, 0.f, 0.f, 0.f);
#pragma unroll
    for (int i = 0; i < DIM / 4; i++) {
        float4 x = v[i];
        a.x = fmaf(x.x, x.x, a.x);
        a.y = fmaf(x.y, x.y, a.y);
        a.z = fmaf(x.z, x.z, a.z);
        a.w = fmaf(x.w, x.w, a.w);
    }
    g_cnorm[idx] = (a.x + a.y) + (a.z + a.w);
}

// 4x2 register micro-tile: warp = 1 token-group (4 tokens) x 32 cw-lanes.
// Thread covers codewords {cl, cl+32} of each 64-cw chunk.
// rf loads are warp-uniform (broadcast, 1 wf); cf loads are 32 rows stride
// RPAD (132 % 32 == 4 -> each quarter-warp tiles all 32 banks, conflict-free).
__global__ void __launch_bounds__(TPB)
rvq_step_kernel(const float* __restrict__ emb,
                const float* __restrict__ cb,   // this codebook [K, D]
                int cb_idx, int use_emb) {
    __shared__ float s_r[MT * RPAD];
    __shared__ float s_c[KTILE * RPAD];
    __shared__ float s_cn[KTILE];

    const float* src = use_emb ? emb : (const float*)g_residual;
    const float* cn  = g_cnorm + (size_t)cb_idx * KCB;

    const int tid = threadIdx.x;
    const int tg  = tid >> 5;       // warp id = token group (0..3)
    const int cl  = tid & 31;       // cw lane (0..31)
    const int tok0 = blockIdx.x * MT;

    // ---- load residual tile [MT x DIM] (coalesced, padded rows) ----
    {
        const int nvec = MT * (DIM / 4);           // 512 float4
#pragma unroll
        for (int t = 0; t < nvec / TPB; t++) {
            int idx = tid + t * TPB;
            int row = idx >> 5;
            int col = idx & 31;
            float4 v = *(const float4*)(src + ((size_t)(tok0 + row)) * DIM + col * 4);
            *(float4*)(s_r + row * RPAD + col * 4) = v;
        }
    }
    __syncthreads();

    // ---- rn for this warp's 4 tokens (same float4-tree order) ----
    float rn[4];
#pragma unroll
    for (int jm = 0; jm < 4; jm++) {
        const float* rr = s_r + (tg * 4 + jm) * RPAD;
        float4 a = make_float4(0.f, 0.f, 0.f, 0.f);
#pragma unroll
        for (int i = 0; i < DIM / 4; i++) {
            float4 x = *(const float4*)(rr + i * 4);
            a.x = fmaf(x.x, x.x, a.x);
            a.y = fmaf(x.y, x.y, a.y);
            a.z = fmaf(x.z, x.z, a.z);
            a.w = fmaf(x.w, x.w, a.w);
        }
        rn[jm] = (a.x + a.y) + (a.z + a.w);
    }

    float bestd[4] = {CUDART_INF_F, CUDART_INF_F, CUDART_INF_F, CUDART_INF_F};
    int   bestk[4] = {0, 0, 0, 0};

#pragma unroll 1
    for (int chunk = 0; chunk < KCB; chunk += KTILE) {
        __syncthreads();
        // cooperative load of codeword chunk [KTILE x DIM]
        {
            const int nvec = KTILE * (DIM / 4);    // 2048 float4
#pragma unroll
            for (int t = 0; t < nvec / TPB; t++) {
                int idx = tid + t * TPB;
                int row = idx >> 5;
                int col = idx & 31;
                float4 v = *(const float4*)(cb + ((size_t)(chunk + row)) * DIM + col * 4);
                *(float4*)(s_c + row * RPAD + col * 4) = v;
            }
            if (tid < KTILE) s_cn[tid] = cn[chunk + tid];
        }
        __syncthreads();

        // 4 tokens x 2 codewords micro-tile (85-ish live regs, spill-free)
        float4 acc[4][2];
#pragma unroll
        for (int jm = 0; jm < 4; jm++) {
            acc[jm][0] = make_float4(0.f, 0.f, 0.f, 0.f);
            acc[jm][1] = make_float4(0.f, 0.f, 0.f, 0.f);
        }

        const float* rbase = s_r + (tg * 4) * RPAD;
        const float* cbase = s_c + cl * RPAD;

#pragma unroll 4
        for (int i = 0; i < DIM / 4; i++) {
            float4 cf0 = *(const float4*)(cbase + i * 4);
            float4 cf1 = *(const float4*)(cbase + 32 * RPAD + i * 4);
            float4 rf[4];
#pragma unroll
            for (int jm = 0; jm < 4; jm++)
                rf[jm] = *(const float4*)(rbase + jm * RPAD + i * 4);
#pragma unroll
            for (int jm = 0; jm < 4; jm++) {
                acc[jm][0].x = fmaf(rf[jm].x, cf0.x, acc[jm][0].x);
                acc[jm][0].y = fmaf(rf[jm].y, cf0.y, acc[jm][0].y);
                acc[jm][0].z = fmaf(rf[jm].z, cf0.z, acc[jm][0].z);
                acc[jm][0].w = fmaf(rf[jm].w, cf0.w, acc[jm][0].w);
                acc[jm][1].x = fmaf(rf[jm].x, cf1.x, acc[jm][1].x);
                acc[jm][1].y = fmaf(rf[jm].y, cf1.y, acc[jm][1].y);
                acc[jm][1].z = fmaf(rf[jm].z, cf1.z, acc[jm][1].z);
                acc[jm][1].w = fmaf(rf[jm].w, cf1.w, acc[jm][1].w);
            }
        }

        // distances + running first-min (k ascending: jc=0 before jc=1)
        float cn0 = s_cn[cl];
        float cn1 = s_cn[cl + 32];
#pragma unroll
        for (int jm = 0; jm < 4; jm++) {
            float4 a0 = acc[jm][0];
            float4 a1 = acc[jm][1];
            float dot0 = (a0.x + a0.y) + (a0.z + a0.w);
            float dot1 = (a1.x + a1.y) + (a1.z + a1.w);
            float d0 = fmaf(-2.f, dot0, rn[jm]) + cn0;
            float d1 = fmaf(-2.f, dot1, rn[jm]) + cn1;
            if (d0 < bestd[jm]) { bestd[jm] = d0; bestk[jm] = chunk + cl; }
            if (d1 < bestd[jm]) { bestd[jm] = d1; bestk[jm] = chunk + cl + 32; }
        }
    }

    // ---- full-warp reduction (min d; tie -> min k); all lanes get result ----
#pragma unroll
    for (int jm = 0; jm < 4; jm++) {
        float bd = bestd[jm];
        int   bk = bestk[jm];
#pragma unroll
        for (int off = 16; off; off >>= 1) {
            float od = __shfl_xor_sync(0xFFFFFFFFu, bd, off);
            int   ok = __shfl_xor_sync(0xFFFFFFFFu, bk, off);
            if (od < bd || (od == bd && ok < bk)) { bd = od; bk = ok; }
        }
        bestd[jm] = bd;
        bestk[jm] = bk;
    }

    // ---- epilogue: lanes 0..3 each own one token (parallel gather) ----
    double lsum = 0.0;
    if (cl < 4) {
        int jm = cl;
        int n = tok0 + tg * 4 + jm;
        int k = bestk[jm];
        const float4* qv = (const float4*)(cb + (size_t)k * DIM);
        const float*  rr = s_r + (tg * 4 + jm) * RPAD;
        float4* rv = (float4*)(g_residual + (size_t)n * DIM);
#pragma unroll
        for (int i = 0; i < DIM / 4; i++) {
            float4 r = *(const float4*)(rr + i * 4);
            float4 q = qv[i];
            r.x -= q.x; r.y -= q.y; r.z -= q.z; r.w -= q.w;
            lsum += (double)r.x * (double)r.x;
            lsum += (double)r.y * (double)r.y;
            lsum += (double)r.z * (double)r.z;
            lsum += (double)r.w * (double)r.w;
            rv[i] = r;
        }
        g_codes[n * NCB + cb_idx] = k;
    }
    // warp-reduce loss (only lanes 0..3 nonzero), one atomic per warp
#pragma unroll
    for (int off = 16; off; off >>= 1)
        lsum += __shfl_down_sync(0xFFFFFFFFu, lsum, off);
    if (cl == 0) atomicAdd(&g_loss[cb_idx], lsum);
}

__global__ void finalize_kernel(const float* __restrict__ emb,
                                const float* __restrict__ cbs,
                                float* oc, float* oq, float* ol) {
    int n = blockIdx.x * blockDim.x + threadIdx.x;
    if (n >= N_TOK) return;

    float4 q[DIM / 4];
#pragma unroll
    for (int i = 0; i < DIM / 4; i++) q[i] = make_float4(0.f, 0.f, 0.f, 0.f);

#pragma unroll 1
    for (int c = 0; c < NCB; c++) {
        int k = g_codes[n * NCB + c];
        const float4* w = (const float4*)(cbs + ((size_t)c * KCB + k) * DIM);
#pragma unroll
        for (int i = 0; i < DIM / 4; i++) {
            float4 x = w[i];
            q[i].x += x.x; q[i].y += x.y; q[i].z += x.z; q[i].w += x.w;
        }
        if (oc) oc[n * NCB + c] = (float)k;
    }

    if (oq) {
        const float4* ev = (const float4*)(emb + (size_t)n * DIM);
        float4* ov = (float4*)(oq + (size_t)n * DIM);
#pragma unroll
        for (int i = 0; i < DIM / 4; i++) {
            float4 e = ev[i];
            float4 o;
            o.x = e.x + (q[i].x - e.x);
            o.y = e.y + (q[i].y - e.y);
            o.z = e.z + (q[i].z - e.z);
            o.w = e.w + (q[i].w - e.w);
            ov[i] = o;
        }
    }

    if (n == 0 && ol) {
        float l = 0.f;
#pragma unroll 1
        for (int c = 0; c < NCB; c++)
            l = l + (float)(g_loss[c] / (double)((size_t)N_TOK * DIM));
        *ol = l / (float)NCB;
    }
}

extern "C" void kernel_launch(void* const* d_in, const int* in_sizes, int n_in,
                              void* d_out, int out_size) {
    const float* emb = (const float*)d_in[0];  // embeddings [8,4096,128] f32
    const float* cbs = (const float*)d_in[1];  // codebooks  [8,1024,128] f32
    float* out = (float*)d_out;

    const long CODES_ELEMS = (long)N_TOK * NCB;        // 262144
    const long QUANT_ELEMS = (long)N_TOK * DIM;        // 4194304
    const long TOTAL = CODES_ELEMS + QUANT_ELEMS + 1;  // 4456449

    float *oc = nullptr, *oq = nullptr, *ol = nullptr;
    if ((long)out_size == TOTAL) {
        oc = out; oq = out + CODES_ELEMS; ol = out + CODES_ELEMS + QUANT_ELEMS;
    } else if ((long)out_size == QUANT_ELEMS) {
        oq = out;
    } else if ((long)out_size == CODES_ELEMS) {
        oc = out;
    } else if (out_size == 1) {
        ol = out;
    } else {
        oc = out;
        if ((long)out_size >= CODES_ELEMS + QUANT_ELEMS) oq = out + CODES_ELEMS;
        if ((long)out_size >= TOTAL) ol = out + CODES_ELEMS + QUANT_ELEMS;
    }

    zero_loss_kernel<<<1, 32>>>();
    cnorm_kernel<<<(NCB * KCB + 127) / 128, 128>>>(cbs);

    for (int c = 0; c < NCB; c++) {
        const float* cb = cbs + (size_t)c * KCB * DIM;
        rvq_step_kernel<<<N_TOK / MT, TPB>>>(emb, cb, c, c == 0 ? 1 : 0);
    }

    finalize_kernel<<<(N_TOK + 127) / 128, 128>>>(emb, cbs, oc, oq, ol);
}

// round 11
// speedup vs baseline: 1.6526x; 1.1912x over previous
#include <cuda_runtime.h>
#include <math_constants.h>

#define N_TOK 32768   // B*T
#define DIM   128
#define KCB   1024
#define NCB   8

#define MT     64     // tokens per block
#define CCHUNK 128    // codewords per smem chunk
#define TPB    128    // 4 warps
#define PAD    132    // smem row stride in 32-bit words

__device__ float    g_residual[N_TOK * DIM];
__device__ unsigned g_cb_tf32[NCB * KCB * DIM];   // pre-converted codebooks
__device__ float    g_cnorm[NCB * KCB];
__device__ int      g_codes[N_TOK * NCB];
__device__ double   g_loss[NCB];

__device__ __forceinline__ unsigned f2tf32(float f) {
    unsigned u;
    asm("cvt.rna.tf32.f32 %0, %1;" : "=r"(u) : "f"(f));
    return u;
}

__device__ __forceinline__ void mma_tf32(float& d0, float& d1, float& d2, float& d3,
                                         unsigned a0, unsigned a1, unsigned a2, unsigned a3,
                                         unsigned b0, unsigned b1) {
    asm volatile(
        "mma.sync.aligned.m16n8k8.row.col.f32.tf32.tf32.f32 "
        "{%0,%1,%2,%3}, {%4,%5,%6,%7}, {%8,%9}, {%0,%1,%2,%3};"
        : "+f"(d0), "+f"(d1), "+f"(d2), "+f"(d3)
        : "r"(a0), "r"(a1), "r"(a2), "r"(a3), "r"(b0), "r"(b1));
}

// lexicographic (d, k) top-3 insert, ascending
__device__ __forceinline__ void ins3(float* d, int* k, float nd, int nk) {
    if (nd < d[2] || (nd == d[2] && nk < k[2])) {
        d[2] = nd; k[2] = nk;
        if (d[2] < d[1] || (d[2] == d[1] && k[2] < k[1])) {
            float td = d[1]; d[1] = d[2]; d[2] = td;
            int   tk = k[1]; k[1] = k[2]; k[2] = tk;
            if (d[1] < d[0] || (d[1] == d[0] && k[1] < k[0])) {
                td = d[0]; d[0] = d[1]; d[1] = td;
                tk = k[0]; k[0] = k[1]; k[1] = tk;
            }
        }
    }
}

__global__ void zero_loss_kernel() {
    if (threadIdx.x < NCB) g_loss[threadIdx.x] = 0.0;
}

__global__ void cnorm_kernel(const float* __restrict__ cbs) {
    int idx = blockIdx.x * blockDim.x + threadIdx.x;
    if (idx >= NCB * KCB) return;
    const float4* v = (const float4*)(cbs + (size_t)idx * DIM);
    float4 a = make_float4(0.f, 0.f, 0.f, 0.f);
#pragma unroll
    for (int i = 0; i < DIM / 4; i++) {
        float4 x = v[i];
        a.x = fmaf(x.x, x.x, a.x);
        a.y = fmaf(x.y, x.y, a.y);
        a.z = fmaf(x.z, x.z, a.z);
        a.w = fmaf(x.w, x.w, a.w);
    }
    g_cnorm[idx] = (a.x + a.y) + (a.z + a.w);
}

__global__ void cvt_cb_kernel(const float* __restrict__ cbs) {
    int i = blockIdx.x * blockDim.x + threadIdx.x;
    if (i < NCB * KCB * DIM) g_cb_tf32[i] = f2tf32(cbs[i]);
}

// One RVQ step: tf32 MMA distance pass + top-3 + exact fp32 rescore + residual update.
__global__ void __launch_bounds__(TPB)
rvq_step_mma(const float* __restrict__ emb,
             const float* __restrict__ cb,     // this codebook fp32 [K, D]
             int cb_idx, int use_emb) {
    extern __shared__ unsigned char smem_raw[];
    unsigned* s_r  = (unsigned*)smem_raw;            // MT*PAD  (tf32 residual)
    unsigned* s_c  = s_r + MT * PAD;                 // CCHUNK*PAD (tf32 codewords)
    float*    s_cn = (float*)(s_c + CCHUNK * PAD);   // CCHUNK
    float*    s_rn = s_cn + CCHUNK;                  // MT
    float*    s_td = s_rn + MT;                      // 4*MT*3
    int*      s_tk = (int*)(s_td + 4 * MT * 3);      // 4*MT*3

    const float*    src = use_emb ? emb : (const float*)g_residual;
    const float*    cn  = g_cnorm + (size_t)cb_idx * KCB;
    const unsigned* cbt = g_cb_tf32 + (size_t)cb_idx * KCB * DIM;

    const int tid  = threadIdx.x;
    const int w    = tid >> 5;
    const int lane = tid & 31;
    const int gid  = lane >> 2;      // 0..7
    const int t4   = lane & 3;       // 0..3
    const int tok0 = blockIdx.x * MT;
    const int cw0w = w * 32;         // warp's cw slice within the chunk

    // ---- fill s_r (tf32) from exact residual ----
    for (int idx = tid; idx < MT * 32; idx += TPB) {
        int tok = idx >> 5, q = idx & 31;
        float4 v = *(const float4*)(src + (size_t)(tok0 + tok) * DIM + q * 4);
        unsigned* d = s_r + tok * PAD + q * 4;
        d[0] = f2tf32(v.x); d[1] = f2tf32(v.y);
        d[2] = f2tf32(v.z); d[3] = f2tf32(v.w);
    }
    // ---- exact rn per token (float4-lane tree, same as passing kernels) ----
    if (tid < MT) {
        const float4* rr = (const float4*)(src + (size_t)(tok0 + tid) * DIM);
        float4 a = make_float4(0.f, 0.f, 0.f, 0.f);
#pragma unroll
        for (int i = 0; i < DIM / 4; i++) {
            float4 x = rr[i];
            a.x = fmaf(x.x, x.x, a.x);
            a.y = fmaf(x.y, x.y, a.y);
            a.z = fmaf(x.z, x.z, a.z);
            a.w = fmaf(x.w, x.w, a.w);
        }
        s_rn[tid] = (a.x + a.y) + (a.z + a.w);
    }
    __syncthreads();

    // lane's 8 tokens: mb*16 + gid + h*8
    float rnl[8];
#pragma unroll
    for (int mb = 0; mb < 4; mb++)
#pragma unroll
        for (int h = 0; h < 2; h++)
            rnl[mb * 2 + h] = s_rn[mb * 16 + gid + h * 8];

    float t3d[8][3];
    int   t3k[8][3];
#pragma unroll
    for (int t = 0; t < 8; t++)
#pragma unroll
        for (int j = 0; j < 3; j++) { t3d[t][j] = CUDART_INF_F; t3k[t][j] = 0x7FFFFFFF; }

#pragma unroll 1
    for (int ch = 0; ch < KCB; ch += CCHUNK) {
        __syncthreads();
        // fill codeword chunk (pre-converted tf32) + norms
        for (int idx = tid; idx < CCHUNK * 32; idx += TPB) {
            int row = idx >> 5, q = idx & 31;
            uint4 v = *(const uint4*)(cbt + (size_t)(ch + row) * DIM + q * 4);
            *(uint4*)(s_c + row * PAD + q * 4) = v;
        }
        if (tid < CCHUNK) s_cn[tid] = cn[ch + tid];
        __syncthreads();

        float cnl[8];
#pragma unroll
        for (int nb = 0; nb < 4; nb++)
#pragma unroll
            for (int jj = 0; jj < 2; jj++)
                cnl[nb * 2 + jj] = s_cn[cw0w + nb * 8 + 2 * t4 + jj];

        float acc[4][4][4];
#pragma unroll
        for (int mb = 0; mb < 4; mb++)
#pragma unroll
            for (int nb = 0; nb < 4; nb++)
#pragma unroll
                for (int j = 0; j < 4; j++) acc[mb][nb][j] = 0.f;

        const unsigned* cbase = s_c + cw0w * PAD;

#pragma unroll 1
        for (int k0 = 0; k0 < DIM; k0 += 8) {
            unsigned a[4][4], b[4][2];
#pragma unroll
            for (int mb = 0; mb < 4; mb++) {
                const unsigned* r0 = s_r + (mb * 16 + gid) * PAD + k0 + t4;
                const unsigned* r1 = s_r + (mb * 16 + gid + 8) * PAD + k0 + t4;
                a[mb][0] = r0[0];
                a[mb][1] = r1[0];
                a[mb][2] = r0[4];
                a[mb][3] = r1[4];
            }
#pragma unroll
            for (int nb = 0; nb < 4; nb++) {
                const unsigned* c0 = cbase + (nb * 8 + gid) * PAD + k0 + t4;
                b[nb][0] = c0[0];
                b[nb][1] = c0[4];
            }
#pragma unroll
            for (int mb = 0; mb < 4; mb++)
#pragma unroll
                for (int nb = 0; nb < 4; nb++)
                    mma_tf32(acc[mb][nb][0], acc[mb][nb][1], acc[mb][nb][2], acc[mb][nb][3],
                             a[mb][0], a[mb][1], a[mb][2], a[mb][3],
                             b[nb][0], b[nb][1]);
        }

        // distances -> top-3
#pragma unroll
        for (int mb = 0; mb < 4; mb++) {
#pragma unroll
            for (int nb = 0; nb < 4; nb++) {
#pragma unroll
                for (int j = 0; j < 4; j++) {
                    int h = j >> 1, jj = j & 1;
                    int ti = mb * 2 + h;
                    int cwl = cw0w + nb * 8 + 2 * t4 + jj;
                    float d = fmaf(-2.f, acc[mb][nb][j], rnl[ti]) + cnl[nb * 2 + jj];
                    ins3(t3d[ti], t3k[ti], d, ch + cwl);
                }
            }
        }
    }

    // ---- merge top-3 across the 4-lane (t4) group ----
#pragma unroll
    for (int off = 1; off <= 2; off <<= 1) {
#pragma unroll
        for (int t = 0; t < 8; t++) {
#pragma unroll
            for (int j = 0; j < 3; j++) {
                float od = __shfl_xor_sync(0xFFFFFFFFu, t3d[t][j], off);
                int   ok = __shfl_xor_sync(0xFFFFFFFFu, t3k[t][j], off);
                ins3(t3d[t], t3k[t], od, ok);
            }
        }
    }
    // per-warp results to smem (lane t4==0 of each gid)
    if (t4 == 0) {
#pragma unroll
        for (int mb = 0; mb < 4; mb++) {
#pragma unroll
            for (int h = 0; h < 2; h++) {
                int tok = mb * 16 + gid + h * 8;
                int ti = mb * 2 + h;
#pragma unroll
                for (int j = 0; j < 3; j++) {
                    s_td[(w * MT + tok) * 3 + j] = t3d[ti][j];
                    s_tk[(w * MT + tok) * 3 + j] = t3k[ti][j];
                }
            }
        }
    }
    __syncthreads();

    // ---- final per-token: merge 4 warps, exact rescore top-3, epilogue ----
    double lsum = 0.0;
    if (tid < MT) {
        const int tok = tid;
        const int n = tok0 + tok;
        float bd[3]; int bk[3];
#pragma unroll
        for (int j = 0; j < 3; j++) { bd[j] = CUDART_INF_F; bk[j] = 0x7FFFFFFF; }
#pragma unroll
        for (int w2 = 0; w2 < 4; w2++)
#pragma unroll
            for (int j = 0; j < 3; j++)
                ins3(bd, bk, s_td[(w2 * MT + tok) * 3 + j], s_tk[(w2 * MT + tok) * 3 + j]);

        // exact rescore (byte-identical formula to the rel_err=0.0 kernels)
        float rnv = s_rn[tok];
        float4 r[DIM / 4];
        const float4* rr = (const float4*)(src + (size_t)n * DIM);
#pragma unroll
        for (int i = 0; i < DIM / 4; i++) r[i] = rr[i];

        float bestd = CUDART_INF_F;
        int   bestk = 0x7FFFFFFF;
#pragma unroll 1
        for (int c = 0; c < 3; c++) {
            int k = bk[c];
            const float4* cv = (const float4*)(cb + (size_t)k * DIM);
            float4 a = make_float4(0.f, 0.f, 0.f, 0.f);
#pragma unroll
            for (int i = 0; i < DIM / 4; i++) {
                float4 x = cv[i];
                a.x = fmaf(r[i].x, x.x, a.x);
                a.y = fmaf(r[i].y, x.y, a.y);
                a.z = fmaf(r[i].z, x.z, a.z);
                a.w = fmaf(r[i].w, x.w, a.w);
            }
            float dot = (a.x + a.y) + (a.z + a.w);
            float d = fmaf(-2.f, dot, rnv) + cn[k];
            if (d < bestd || (d == bestd && k < bestk)) { bestd = d; bestk = k; }
        }

        // residual update + loss (identical to passing epilogue)
        const float4* qv = (const float4*)(cb + (size_t)bestk * DIM);
        float4* rv = (float4*)(g_residual + (size_t)n * DIM);
#pragma unroll
        for (int i = 0; i < DIM / 4; i++) {
            float4 rr2 = r[i];
            float4 q = qv[i];
            rr2.x -= q.x; rr2.y -= q.y; rr2.z -= q.z; rr2.w -= q.w;
            lsum += (double)rr2.x * (double)rr2.x;
            lsum += (double)rr2.y * (double)rr2.y;
            lsum += (double)rr2.z * (double)rr2.z;
            lsum += (double)rr2.w * (double)rr2.w;
            rv[i] = rr2;
        }
        g_codes[n * NCB + cb_idx] = bestk;
    }
    // loss: warp reduce + one atomic per active warp (warps 0,1)
#pragma unroll
    for (int off = 16; off; off >>= 1)
        lsum += __shfl_down_sync(0xFFFFFFFFu, lsum, off);
    if (lane == 0 && w < 2) atomicAdd(&g_loss[cb_idx], lsum);
}

__global__ void finalize_kernel(const float* __restrict__ emb,
                                const float* __restrict__ cbs,
                                float* oc, float* oq, float* ol) {
    int n = blockIdx.x * blockDim.x + threadIdx.x;
    if (n >= N_TOK) return;

    float4 q[DIM / 4];
#pragma unroll
    for (int i = 0; i < DIM / 4; i++) q[i] = make_float4(0.f, 0.f, 0.f, 0.f);

#pragma unroll 1
    for (int c = 0; c < NCB; c++) {
        int k = g_codes[n * NCB + c];
        const float4* w = (const float4*)(cbs + ((size_t)c * KCB + k) * DIM);
#pragma unroll
        for (int i = 0; i < DIM / 4; i++) {
            float4 x = w[i];
            q[i].x += x.x; q[i].y += x.y; q[i].z += x.z; q[i].w += x.w;
        }
        if (oc) oc[n * NCB + c] = (float)k;
    }

    if (oq) {
        const float4* ev = (const float4*)(emb + (size_t)n * DIM);
        float4* ov = (float4*)(oq + (size_t)n * DIM);
#pragma unroll
        for (int i = 0; i < DIM / 4; i++) {
            float4 e = ev[i];
            float4 o;
            o.x = e.x + (q[i].x - e.x);
            o.y = e.y + (q[i].y - e.y);
            o.z = e.z + (q[i].z - e.z);
            o.w = e.w + (q[i].w - e.w);
            ov[i] = o;
        }
    }

    if (n == 0 && ol) {
        float l = 0.f;
#pragma unroll 1
        for (int c = 0; c < NCB; c++)
            l = l + (float)(g_loss[c] / (double)((size_t)N_TOK * DIM));
        *ol = l / (float)NCB;
    }
}

extern "C" void kernel_launch(void* const* d_in, const int* in_sizes, int n_in,
                              void* d_out, int out_size) {
    const float* emb = (const float*)d_in[0];  // [8,4096,128] f32
    const float* cbs = (const float*)d_in[1];  // [8,1024,128] f32
    float* out = (float*)d_out;

    const long CODES_ELEMS = (long)N_TOK * NCB;
    const long QUANT_ELEMS = (long)N_TOK * DIM;
    const long TOTAL = CODES_ELEMS + QUANT_ELEMS + 1;

    float *oc = nullptr, *oq = nullptr, *ol = nullptr;
    if ((long)out_size == TOTAL) {
        oc = out; oq = out + CODES_ELEMS; ol = out + CODES_ELEMS + QUANT_ELEMS;
    } else if ((long)out_size == QUANT_ELEMS) {
        oq = out;
    } else if ((long)out_size == CODES_ELEMS) {
        oc = out;
    } else if (out_size == 1) {
        ol = out;
    } else {
        oc = out;
        if ((long)out_size >= CODES_ELEMS + QUANT_ELEMS) oq = out + CODES_ELEMS;
        if ((long)out_size >= TOTAL) ol = out + CODES_ELEMS + QUANT_ELEMS;
    }

    const int SMEM_BYTES = (MT * PAD + CCHUNK * PAD) * 4   // tf32 tiles
                         + CCHUNK * 4 + MT * 4             // cn, rn
                         + 4 * MT * 3 * 4 * 2;             // top-3 d/k
    cudaFuncSetAttribute(rvq_step_mma,
                         cudaFuncAttributeMaxDynamicSharedMemorySize, SMEM_BYTES);

    zero_loss_kernel<<<1, 32>>>();
    cnorm_kernel<<<(NCB * KCB + 127) / 128, 128>>>(cbs);
    cvt_cb_kernel<<<(NCB * KCB * DIM + 255) / 256, 256>>>(cbs);

    for (int c = 0; c < NCB; c++) {
        const float* cb = cbs + (size_t)c * KCB * DIM;
        rvq_step_mma<<<N_TOK / MT, TPB, SMEM_BYTES>>>(emb, cb, c, c == 0 ? 1 : 0);
    }

    finalize_kernel<<<(N_TOK + 127) / 128, 128>>>(emb, cbs, oc, oq, ol);
}